// round 8
// baseline (speedup 1.0000x reference)
#include <cuda_runtime.h>

#define N     8192
#define DIM   128
#define E     262144
#define NBLK  148
#define T     256
#define GT    (NBLK * T)
#define NWARP (GT / 32)
#define ASTR  132   // padded A row stride (floats)

// Scratch (device globals -- allocation-free per harness rules)
__device__ float g_inv_nrm[N];
__device__ float g_dis[N];            // rsqrt(deg+1)
__device__ int   g_cnt[N];            // in-degree histogram (zeroed at end of each run)
__device__ int   g_startA[N + 1];     // CSR starts + sentinel E
__device__ int   g_cursor[N];         // fill cursors
__device__ int   g_csr[E];            // CSR source node per slot
__device__ float g_M[DIM * DIM];      // Y^T x (zeroed at end of each run)
__device__ float g_dxw[N * DIM];      // x @ W (unscaled)
__device__ float g_gate[N * DIM];     // sigmoid(y . M)
__device__ unsigned g_arrive;
__device__ volatile unsigned g_gen;

// -------- software grid barrier: valid because grid == 148 == #SMs (1 wave)
__device__ __forceinline__ void gridbar() {
    __syncthreads();
    if (threadIdx.x == 0) {
        __threadfence();
        unsigned gen = g_gen;
        if (atomicAdd(&g_arrive, 1) == NBLK - 1) {
            g_arrive = 0;
            __threadfence();
            g_gen = gen + 1;
        } else {
            while (g_gen == gen) { }
        }
        __threadfence();
    }
    __syncthreads();
}

// -------- packed fp32x2 helpers
__device__ __forceinline__ unsigned long long pk2(float lo, float hi) {
    unsigned long long r;
    asm("mov.b64 %0, {%1, %2};" : "=l"(r) : "f"(lo), "f"(hi));
    return r;
}
__device__ __forceinline__ void fma2(unsigned long long& d, unsigned long long a,
                                     unsigned long long b) {
    asm("fma.rn.f32x2 %0, %1, %2, %0;" : "+l"(d) : "l"(a), "l"(b));
}
__device__ __forceinline__ void unpk(unsigned long long v, float& lo, float& hi) {
    asm("mov.b64 {%0, %1}, %2;" : "=f"(lo), "=f"(hi) : "l"(v));
}

// -------- M = Y^T x panel (64 rows), fused row norms, atomics into g_M
__device__ void maccum_panel(const float* __restrict__ x, int panel, int tid) {
    __shared__ float xs[8][DIM];
    __shared__ float invs[8];
    int tx = tid & 15, ty = tid >> 4;
    int k0 = ty * 8, d0 = tx * 8;
    float acc[8][8] = {};
    int row_base = panel * 64;
    for (int p = 0; p < 8; p++) {
        int r0 = row_base + p * 8;
        {
            int rr = tid >> 5, cc = tid & 31;
            float4 v = ((const float4*)x)[(r0 + rr) * 32 + cc];
            ((float4*)&xs[rr][0])[cc] = v;
            float s = v.x * v.x + v.y * v.y + v.z * v.z + v.w * v.w;
            #pragma unroll
            for (int o = 16; o; o >>= 1) s += __shfl_xor_sync(0xffffffffu, s, o);
            if (cc == 0) {
                float inv = rsqrtf(s);
                invs[rr] = inv;
                g_inv_nrm[r0 + rr] = inv;
            }
        }
        __syncthreads();
        #pragma unroll
        for (int r = 0; r < 8; r++) {
            float inv = invs[r];
            float yk[8], xd[8];
            #pragma unroll
            for (int j = 0; j < 8; j++) yk[j] = xs[r][k0 + j] * inv;
            #pragma unroll
            for (int l = 0; l < 8; l++) xd[l] = xs[r][d0 + l];
            #pragma unroll
            for (int j = 0; j < 8; j++)
                #pragma unroll
                for (int l = 0; l < 8; l++)
                    acc[j][l] += yk[j] * xd[l];
        }
        __syncthreads();
    }
    #pragma unroll
    for (int j = 0; j < 8; j++)
        #pragma unroll
        for (int l = 0; l < 8; l++)
            atomicAdd(&g_M[(k0 + j) * DIM + (d0 + l)], acc[j][l]);
}

// -------- scan 8192 counts on one block (256 threads x 32 counters)
__device__ void scan_256(int tid) {
    __shared__ int wsum[8];
    int base = tid * 32;
    int c[32], s = 0;
    const int4* cp = (const int4*)(g_cnt + base);
    #pragma unroll
    for (int j = 0; j < 8; j++) {
        int4 v = cp[j];
        c[4*j] = v.x; c[4*j+1] = v.y; c[4*j+2] = v.z; c[4*j+3] = v.w;
        s += v.x + v.y + v.z + v.w;
    }
    int lane = tid & 31, w = tid >> 5;
    int v = s;
    #pragma unroll
    for (int o = 1; o < 32; o <<= 1) {
        int t = __shfl_up_sync(0xffffffffu, v, o);
        if (lane >= o) v += t;
    }
    if (lane == 31) wsum[w] = v;
    __syncthreads();
    if (w == 0 && lane < 8) {
        int t = wsum[lane];
        #pragma unroll
        for (int o = 1; o < 8; o <<= 1) {
            int u = __shfl_up_sync(0xffu, t, o);
            if (lane >= o) t += u;
        }
        wsum[lane] = t;
    }
    __syncthreads();
    int run = v - s + (w > 0 ? wsum[w - 1] : 0);
    #pragma unroll
    for (int j = 0; j < 32; j++) {
        g_startA[base + j] = run;
        g_cursor[base + j] = run;
        g_dis[base + j]    = rsqrtf((float)(c[j] + 1));
        run += c[j];
    }
    if (tid == 255) g_startA[N] = run;   // == E
}

// -------- GEMM helpers (64x128 tile per block, f32x2 inner product)
__device__ __forceinline__ void stage_A(const float* __restrict__ x, float* As,
                                        int rb, int tid) {
    #pragma unroll
    for (int i = 0; i < 8; i++) {
        int f = i * 256 + tid;
        int row = f >> 5, c4 = f & 31;
        float4 v = ((const float4*)x)[(rb + row) * 32 + c4];
        *((float4*)&As[row * ASTR + c4 * 4]) = v;
    }
}
__device__ __forceinline__ void stage_B(const float* __restrict__ B, float* Bs, int tid) {
    #pragma unroll
    for (int i = 0; i < 16; i++) {
        int f = i * 256 + tid;
        ((float4*)Bs)[f] = ((const float4*)B)[f];
    }
}
__device__ __forceinline__ void gemm_compute(const float* As, const float* Bs,
                                             int r0, int tx,
                                             unsigned long long acc[8][2]) {
    #pragma unroll
    for (int i = 0; i < 8; i++) { acc[i][0] = 0ULL; acc[i][1] = 0ULL; }
    #pragma unroll 4
    for (int k = 0; k < DIM; k++) {
        float4 bv = ((const float4*)Bs)[k * 32 + tx];
        unsigned long long b01 = pk2(bv.x, bv.y);
        unsigned long long b23 = pk2(bv.z, bv.w);
        #pragma unroll
        for (int i = 0; i < 8; i++) {
            float a = As[(r0 + i) * ASTR + k];      // warp-broadcast
            unsigned long long aa = pk2(a, a);
            fma2(acc[i][0], aa, b01);
            fma2(acc[i][1], aa, b23);
        }
    }
}

// ======================= the single persistent kernel =======================
__global__ void __launch_bounds__(T) k_all(const float* __restrict__ x,
                                           const int* __restrict__ ei,
                                           const float* __restrict__ W,
                                           const float* __restrict__ b,
                                           float* __restrict__ out) {
    extern __shared__ float sm[];
    float* As = sm;                 // [64][ASTR]
    float* Bs = sm + 64 * ASTR;     // [128][128]
    int tid = threadIdx.x, bid = blockIdx.x;
    int gtid = bid * T + tid;

    // ---------- P1: maccum (blocks 1..128)  ||  histogram (blocks 0,129..147)
    if (bid >= 1 && bid <= 128) {
        maccum_panel(x, bid - 1, tid);
    } else {
        int hb = (bid == 0) ? 0 : (bid - 128);     // 0..19
        int hid = hb * T + tid;
        const int4* c4p = (const int4*)(ei + E);
        for (int i = hid; i < E / 4; i += 20 * T) {
            int4 c = __ldg(&c4p[i]);
            atomicAdd(&g_cnt[c.x], 1); atomicAdd(&g_cnt[c.y], 1);
            atomicAdd(&g_cnt[c.z], 1); atomicAdd(&g_cnt[c.w], 1);
        }
    }
    gridbar();

    // ---------- P2: scan (block 0)  ||  gemm-W (blocks 1..128)
    if (bid == 0) {
        scan_256(tid);
    } else if (bid <= 128) {
        int rb = (bid - 1) * 64;
        stage_A(x, As, rb, tid);
        stage_B(W, Bs, tid);
        __syncthreads();
        int tx = tid & 31, ty = tid >> 5;
        unsigned long long acc[8][2];
        gemm_compute(As, Bs, ty * 8, tx, acc);
        #pragma unroll
        for (int i = 0; i < 8; i++) {
            float4 o;
            unpk(acc[i][0], o.x, o.y);
            unpk(acc[i][1], o.z, o.w);
            ((float4*)g_dxw)[(rb + ty * 8 + i) * 32 + tx] = o;
        }
    }
    gridbar();

    // ---------- P3: CSR fill (all blocks), then gemm-M (blocks 1..128, A cached)
    {
        const int4* r4p = (const int4*)ei;
        const int4* c4p = (const int4*)(ei + E);
        for (int i = gtid; i < E / 4; i += GT) {
            int4 r = __ldg(&r4p[i]);
            int4 c = __ldg(&c4p[i]);
            g_csr[atomicAdd(&g_cursor[c.x], 1)] = r.x;
            g_csr[atomicAdd(&g_cursor[c.y], 1)] = r.y;
            g_csr[atomicAdd(&g_cursor[c.z], 1)] = r.z;
            g_csr[atomicAdd(&g_cursor[c.w], 1)] = r.w;
        }
    }
    if (bid >= 1 && bid <= 128) {
        __syncthreads();
        stage_B(g_M, Bs, tid);                      // As still holds x rows
        __syncthreads();
        int tx = tid & 31, ty = tid >> 5;
        int rb = (bid - 1) * 64;
        unsigned long long acc[8][2];
        gemm_compute(As, Bs, ty * 8, tx, acc);
        #pragma unroll
        for (int i = 0; i < 8; i++) {
            int grow = rb + ty * 8 + i;
            float s = g_inv_nrm[grow];
            float v0, v1, v2, v3;
            unpk(acc[i][0], v0, v1);
            unpk(acc[i][1], v2, v3);
            float4 o;
            o.x = 1.f / (1.f + __expf(-v0 * s));
            o.y = 1.f / (1.f + __expf(-v1 * s));
            o.z = 1.f / (1.f + __expf(-v2 * s));
            o.w = 1.f / (1.f + __expf(-v3 * s));
            ((float4*)g_gate)[grow * 32 + tx] = o;
        }
    }
    gridbar();

    // ---------- P4: final gather + epilogue; re-zero g_M/g_cnt for next run
    for (int i = gtid; i < DIM * DIM; i += GT) g_M[i] = 0.f;
    for (int i = gtid; i < N; i += GT) g_cnt[i] = 0;

    int gw = gtid >> 5, lane = tid & 31;
    const float4* dxw4 = (const float4*)g_dxw;
    for (int node = gw; node < N; node += NWARP) {
        int s0  = g_startA[node];
        int cnt = g_startA[node + 1] - s0;
        float dn = g_dis[node];
        float4 self = dxw4[node * 32 + lane];
        float4 acc;
        acc.x = self.x * dn; acc.y = self.y * dn;
        acc.z = self.z * dn; acc.w = self.w * dn;
        int j = 0;
        for (; j + 4 <= cnt; j += 4) {
            int i0 = __ldg(&g_csr[s0 + j]);
            int i1 = __ldg(&g_csr[s0 + j + 1]);
            int i2 = __ldg(&g_csr[s0 + j + 2]);
            int i3 = __ldg(&g_csr[s0 + j + 3]);
            float d0 = __ldg(&g_dis[i0]), d1 = __ldg(&g_dis[i1]);
            float d2 = __ldg(&g_dis[i2]), d3 = __ldg(&g_dis[i3]);
            float4 v0 = dxw4[i0 * 32 + lane];
            float4 v1 = dxw4[i1 * 32 + lane];
            float4 v2 = dxw4[i2 * 32 + lane];
            float4 v3 = dxw4[i3 * 32 + lane];
            acc.x += v0.x * d0 + v1.x * d1 + v2.x * d2 + v3.x * d3;
            acc.y += v0.y * d0 + v1.y * d1 + v2.y * d2 + v3.y * d3;
            acc.z += v0.z * d0 + v1.z * d1 + v2.z * d2 + v3.z * d3;
            acc.w += v0.w * d0 + v1.w * d1 + v2.w * d2 + v3.w * d3;
        }
        for (; j < cnt; j++) {
            int i0 = __ldg(&g_csr[s0 + j]);
            float d0 = __ldg(&g_dis[i0]);
            float4 v0 = dxw4[i0 * 32 + lane];
            acc.x += v0.x * d0; acc.y += v0.y * d0;
            acc.z += v0.z * d0; acc.w += v0.w * d0;
        }
        float4 bb = ((const float4*)b)[lane];
        float4 a  = ((const float4*)g_gate)[node * 32 + lane];
        float4 o;
        o.x = (acc.x * dn + bb.x) * a.x;
        o.y = (acc.y * dn + bb.y) * a.y;
        o.z = (acc.z * dn + bb.z) * a.z;
        o.w = (acc.w * dn + bb.w) * a.w;
        ((float4*)out)[node * 32 + lane] = o;
    }
}

// ---------------------------------------------------------------- launcher
extern "C" void kernel_launch(void* const* d_in, const int* in_sizes, int n_in,
                              void* d_out, int out_size) {
    const float* x  = (const float*)d_in[0];
    const int*   ei = (const int*)d_in[1];
    const float* W  = (const float*)d_in[2];
    const float* b  = (const float*)d_in[3];
    float* out = (float*)d_out;

    const int SMEM = (64 * ASTR + 128 * 128) * 4;   // ~97 KB dynamic
    cudaFuncSetAttribute(k_all, cudaFuncAttributeMaxDynamicSharedMemorySize, SMEM);
    k_all<<<NBLK, T, SMEM>>>(x, ei, W, b, out);
}

// round 9
// speedup vs baseline: 1.2260x; 1.2260x over previous
#include <cuda_runtime.h>

#define N     8192
#define DIM   128
#define E     262144
#define T     256
#define ASTR  132   // padded A row stride (floats)

#define NB_MAC  128            // maccum blocks in n1
#define NB_GW   128            // gemm-W blocks in n1
#define NB_HIST 44             // hist blocks in n1
#define NB_ALL  (NB_MAC + NB_GW + NB_HIST)

// Scratch (device globals -- allocation-free; zero-init at load,
// re-zeroed by k_final each run so every invocation sees identical state)
__device__ float g_inv_nrm[N];
__device__ float g_dis[N];
__device__ int   g_cnt[N];
__device__ int   g_startA[N + 1];
__device__ int   g_cursor[N];
__device__ int   g_csr[E];
__device__ float g_M[DIM * DIM];
__device__ float g_dxw[N * DIM];
__device__ float g_gate[N * DIM];

// -------- packed fp32x2 helpers
__device__ __forceinline__ unsigned long long pk2(float lo, float hi) {
    unsigned long long r;
    asm("mov.b64 %0, {%1, %2};" : "=l"(r) : "f"(lo), "f"(hi));
    return r;
}
__device__ __forceinline__ void fma2(unsigned long long& d, unsigned long long a,
                                     unsigned long long b) {
    asm("fma.rn.f32x2 %0, %1, %2, %0;" : "+l"(d) : "l"(a), "l"(b));
}
__device__ __forceinline__ void unpk(unsigned long long v, float& lo, float& hi) {
    asm("mov.b64 {%0, %1}, %2;" : "=f"(lo), "=f"(hi) : "l"(v));
}

// ================== n1: maccum | gemm-W | hist, role by blockIdx ==========
__device__ void maccum_panel(const float* __restrict__ x, int panel, int tid) {
    __shared__ float xs[8][DIM];
    __shared__ float invs[8];
    int tx = tid & 15, ty = tid >> 4;
    int k0 = ty * 8, d0 = tx * 8;
    unsigned long long acc2[8][4];
    #pragma unroll
    for (int j = 0; j < 8; j++)
        #pragma unroll
        for (int l = 0; l < 4; l++) acc2[j][l] = 0ULL;

    int row_base = panel * 64;
    for (int p = 0; p < 8; p++) {
        int r0 = row_base + p * 8;
        {
            int rr = tid >> 5, cc = tid & 31;
            float4 v = ((const float4*)x)[(r0 + rr) * 32 + cc];
            ((float4*)&xs[rr][0])[cc] = v;
            float s = v.x * v.x + v.y * v.y + v.z * v.z + v.w * v.w;
            #pragma unroll
            for (int o = 16; o; o >>= 1) s += __shfl_xor_sync(0xffffffffu, s, o);
            if (cc == 0) {
                float inv = rsqrtf(s);
                invs[rr] = inv;
                g_inv_nrm[r0 + rr] = inv;
            }
        }
        __syncthreads();
        #pragma unroll
        for (int r = 0; r < 8; r++) {
            float inv = invs[r];
            unsigned long long xp[4];
            #pragma unroll
            for (int l = 0; l < 4; l++)
                xp[l] = pk2(xs[r][d0 + 2*l], xs[r][d0 + 2*l + 1]);
            #pragma unroll
            for (int j = 0; j < 8; j++) {
                float yk = xs[r][k0 + j] * inv;
                unsigned long long aa = pk2(yk, yk);
                #pragma unroll
                for (int l = 0; l < 4; l++) fma2(acc2[j][l], aa, xp[l]);
            }
        }
        __syncthreads();
    }
    #pragma unroll
    for (int j = 0; j < 8; j++)
        #pragma unroll
        for (int l = 0; l < 4; l++) {
            float lo, hi;
            unpk(acc2[j][l], lo, hi);
            atomicAdd(&g_M[(k0 + j) * DIM + d0 + 2*l],     lo);
            atomicAdd(&g_M[(k0 + j) * DIM + d0 + 2*l + 1], hi);
        }
}

__device__ __forceinline__ void stage_A(const float* __restrict__ x, float* As,
                                        int rb, int tid) {
    #pragma unroll
    for (int i = 0; i < 8; i++) {
        int f = i * 256 + tid;
        int row = f >> 5, c4 = f & 31;
        float4 v = ((const float4*)x)[(rb + row) * 32 + c4];
        *((float4*)&As[row * ASTR + c4 * 4]) = v;
    }
}
__device__ __forceinline__ void stage_B(const float* __restrict__ B, float* Bs, int tid) {
    #pragma unroll
    for (int i = 0; i < 16; i++) {
        int f = i * 256 + tid;
        ((float4*)Bs)[f] = ((const float4*)B)[f];
    }
}
__device__ __forceinline__ void gemm_compute(const float* As, const float* Bs,
                                             int r0, int tx,
                                             unsigned long long acc[8][2]) {
    #pragma unroll
    for (int i = 0; i < 8; i++) { acc[i][0] = 0ULL; acc[i][1] = 0ULL; }
    #pragma unroll 4
    for (int k = 0; k < DIM; k++) {
        float4 bv = ((const float4*)Bs)[k * 32 + tx];
        unsigned long long b01 = pk2(bv.x, bv.y);
        unsigned long long b23 = pk2(bv.z, bv.w);
        #pragma unroll
        for (int i = 0; i < 8; i++) {
            float a = As[(r0 + i) * ASTR + k];      // warp-broadcast
            unsigned long long aa = pk2(a, a);
            fma2(acc[i][0], aa, b01);
            fma2(acc[i][1], aa, b23);
        }
    }
}

__global__ void __launch_bounds__(T) k_n1(const float* __restrict__ x,
                                          const int* __restrict__ ei,
                                          const float* __restrict__ W) {
    extern __shared__ float sm[];
    int tid = threadIdx.x, bid = blockIdx.x;

    if (bid < NB_MAC) {
        maccum_panel(x, bid, tid);
    } else if (bid < NB_MAC + NB_GW) {
        float* As = sm;
        float* Bs = sm + 64 * ASTR;
        int rb = (bid - NB_MAC) * 64;
        stage_A(x, As, rb, tid);
        stage_B(W, Bs, tid);
        __syncthreads();
        int tx = tid & 31, ty = tid >> 5;
        unsigned long long acc[8][2];
        gemm_compute(As, Bs, ty * 8, tx, acc);
        #pragma unroll
        for (int i = 0; i < 8; i++) {
            float4 o;
            unpk(acc[i][0], o.x, o.y);
            unpk(acc[i][1], o.z, o.w);
            ((float4*)g_dxw)[(rb + ty * 8 + i) * 32 + tx] = o;
        }
    } else {
        int hb = bid - NB_MAC - NB_GW;             // 0..NB_HIST-1
        const int4* c4p = (const int4*)(ei + E);
        for (int i = hb * T + tid; i < E / 4; i += NB_HIST * T) {
            int4 c = __ldg(&c4p[i]);
            atomicAdd(&g_cnt[c.x], 1); atomicAdd(&g_cnt[c.y], 1);
            atomicAdd(&g_cnt[c.z], 1); atomicAdd(&g_cnt[c.w], 1);
        }
    }
}

// ================== scan: 1 block, 1024 threads x 8 counters ==============
__global__ void k_scan() {
    __shared__ int warp_sums[32];
    int tid = threadIdx.x;
    int base = tid * 8;
    int c[8], s = 0;
    #pragma unroll
    for (int j = 0; j < 8; j++) { c[j] = g_cnt[base + j]; s += c[j]; }
    int lane = tid & 31, w = tid >> 5;
    int v = s;
    #pragma unroll
    for (int o = 1; o < 32; o <<= 1) {
        int t = __shfl_up_sync(0xffffffffu, v, o);
        if (lane >= o) v += t;
    }
    if (lane == 31) warp_sums[w] = v;
    __syncthreads();
    if (w == 0) {
        int ws = warp_sums[lane];
        #pragma unroll
        for (int o = 1; o < 32; o <<= 1) {
            int t = __shfl_up_sync(0xffffffffu, ws, o);
            if (lane >= o) ws += t;
        }
        warp_sums[lane] = ws;
    }
    __syncthreads();
    int run = v - s + (w > 0 ? warp_sums[w - 1] : 0);
    #pragma unroll
    for (int j = 0; j < 8; j++) {
        g_startA[base + j] = run;
        g_cursor[base + j] = run;
        g_dis[base + j]    = rsqrtf((float)(c[j] + 1));
        run += c[j];
    }
    if (tid == 1023) g_startA[N] = E;
}

// ================== CSR fill, wide grid ===================================
__global__ void k_fill(const int* __restrict__ ei) {
    int i = blockIdx.x * blockDim.x + threadIdx.x;
    int r = __ldg(&ei[i]);
    int c = __ldg(&ei[E + i]);
    g_csr[atomicAdd(&g_cursor[c], 1)] = r;
}

// ================== gemm-M -> gate (needs n1 complete) ====================
__global__ void __launch_bounds__(T) k_gemmM(const float* __restrict__ x) {
    extern __shared__ float sm[];
    float* As = sm;
    float* Bs = sm + 64 * ASTR;
    int tid = threadIdx.x;
    int rb = blockIdx.x * 64;
    stage_A(x, As, rb, tid);
    stage_B(g_M, Bs, tid);
    __syncthreads();
    int tx = tid & 31, ty = tid >> 5;
    unsigned long long acc[8][2];
    gemm_compute(As, Bs, ty * 8, tx, acc);
    #pragma unroll
    for (int i = 0; i < 8; i++) {
        int grow = rb + ty * 8 + i;
        float s = g_inv_nrm[grow];
        float v0, v1, v2, v3;
        unpk(acc[i][0], v0, v1);
        unpk(acc[i][1], v2, v3);
        float4 o;
        o.x = 1.f / (1.f + __expf(-v0 * s));
        o.y = 1.f / (1.f + __expf(-v1 * s));
        o.z = 1.f / (1.f + __expf(-v2 * s));
        o.w = 1.f / (1.f + __expf(-v3 * s));
        ((float4*)g_gate)[grow * 32 + tx] = o;
    }
}

// ================== final gather + epilogue + state re-zero ===============
__global__ void k_final(const float* __restrict__ b, float* __restrict__ out) {
    int tid = threadIdx.x;
    int gtid = blockIdx.x * T + tid;
    // self-clean for next invocation (nothing below reads g_M / g_cnt)
    if (gtid < DIM * DIM) g_M[gtid] = 0.f;
    if (gtid < N) g_cnt[gtid] = 0;

    int w = tid >> 5, lane = tid & 31;
    int node = blockIdx.x * 8 + w;
    const float4* dxw4 = (const float4*)g_dxw;

    int s0  = g_startA[node];
    int cnt = g_startA[node + 1] - s0;
    float dn = g_dis[node];
    float4 self = dxw4[node * 32 + lane];
    float4 acc;
    acc.x = self.x * dn; acc.y = self.y * dn;
    acc.z = self.z * dn; acc.w = self.w * dn;
    int j = 0;
    for (; j + 4 <= cnt; j += 4) {
        int i0 = __ldg(&g_csr[s0 + j]);
        int i1 = __ldg(&g_csr[s0 + j + 1]);
        int i2 = __ldg(&g_csr[s0 + j + 2]);
        int i3 = __ldg(&g_csr[s0 + j + 3]);
        float d0 = __ldg(&g_dis[i0]), d1 = __ldg(&g_dis[i1]);
        float d2 = __ldg(&g_dis[i2]), d3 = __ldg(&g_dis[i3]);
        float4 v0 = dxw4[i0 * 32 + lane];
        float4 v1 = dxw4[i1 * 32 + lane];
        float4 v2 = dxw4[i2 * 32 + lane];
        float4 v3 = dxw4[i3 * 32 + lane];
        acc.x += v0.x * d0 + v1.x * d1 + v2.x * d2 + v3.x * d3;
        acc.y += v0.y * d0 + v1.y * d1 + v2.y * d2 + v3.y * d3;
        acc.z += v0.z * d0 + v1.z * d1 + v2.z * d2 + v3.z * d3;
        acc.w += v0.w * d0 + v1.w * d1 + v2.w * d2 + v3.w * d3;
    }
    for (; j < cnt; j++) {
        int i0 = __ldg(&g_csr[s0 + j]);
        float d0 = __ldg(&g_dis[i0]);
        float4 v0 = dxw4[i0 * 32 + lane];
        acc.x += v0.x * d0; acc.y += v0.y * d0;
        acc.z += v0.z * d0; acc.w += v0.w * d0;
    }
    float4 bb = ((const float4*)b)[lane];
    float4 a  = ((const float4*)g_gate)[node * 32 + lane];
    float4 o;
    o.x = (acc.x * dn + bb.x) * a.x;
    o.y = (acc.y * dn + bb.y) * a.y;
    o.z = (acc.z * dn + bb.z) * a.z;
    o.w = (acc.w * dn + bb.w) * a.w;
    ((float4*)out)[node * 32 + lane] = o;
}

// ---------------------------------------------------------------- launcher
extern "C" void kernel_launch(void* const* d_in, const int* in_sizes, int n_in,
                              void* d_out, int out_size) {
    const float* x  = (const float*)d_in[0];
    const int*   ei = (const int*)d_in[1];
    const float* W  = (const float*)d_in[2];
    const float* b  = (const float*)d_in[3];
    float* out = (float*)d_out;

    const int SMEM = (64 * ASTR + 128 * 128) * 4;   // ~97 KB
    static bool init_done = false;
    static cudaStream_t sB;
    static cudaEvent_t evN1, evFill;
    if (!init_done) {
        cudaStreamCreateWithFlags(&sB, cudaStreamNonBlocking);
        cudaEventCreateWithFlags(&evN1,   cudaEventDisableTiming);
        cudaEventCreateWithFlags(&evFill, cudaEventDisableTiming);
        cudaFuncSetAttribute(k_n1,    cudaFuncAttributeMaxDynamicSharedMemorySize, SMEM);
        cudaFuncSetAttribute(k_gemmM, cudaFuncAttributeMaxDynamicSharedMemorySize, SMEM);
        init_done = true;
    }

    // n1: maccum | gemm-W | hist (all independent)
    k_n1<<<NB_ALL, T, SMEM>>>(x, ei, W);
    cudaEventRecord(evN1, 0);

    // branch: scan -> fill  (depends on hist in n1)
    cudaStreamWaitEvent(sB, evN1, 0);
    k_scan<<<1, 1024, 0, sB>>>();
    k_fill<<<E / 256, 256, 0, sB>>>(ei);
    cudaEventRecord(evFill, sB);

    // main: gemm-M (depends on n1)
    k_gemmM<<<128, T, SMEM>>>(x);

    // join: final
    cudaStreamWaitEvent(0, evFill, 0);
    k_final<<<N / 8, 256>>>(b, out);
}

// round 10
// speedup vs baseline: 1.6752x; 1.3664x over previous
#include <cuda_runtime.h>

#define N    8192
#define DIM  128
#define E    262144
#define ASTR 132   // padded A row stride (floats)

// Scratch (device globals -- allocation-free; zero-init at load,
// g_M / g_cnt re-zeroed by k_final so each replay sees identical state)
__device__ float g_inv_nrm[N];
__device__ float g_dis[N];            // rsqrt(deg+1)
__device__ int   g_cnt[N];            // in-degree histogram
__device__ int   g_startA[N + 1];     // CSR starts + sentinel E
__device__ int   g_cursor[N];         // fill cursors
__device__ int   g_csr[E];            // CSR source node per slot
__device__ float g_M[DIM * DIM];      // Y^T x
__device__ float g_dxw[N * DIM];      // x @ W (unscaled)
__device__ float g_gate[N * DIM];     // sigmoid(y . M)

// ----------------- chain B1: in-degree histogram, wide grid
__global__ void k_hist(const int* __restrict__ ei) {
    int i = blockIdx.x * blockDim.x + threadIdx.x;
    atomicAdd(&g_cnt[__ldg(&ei[E + i])], 1);
}

// ----------------- chain B2: scan 8192 counts -> start/cursor/dis (1 block)
__global__ void k_scan() {
    __shared__ int warp_sums[32];
    int tid = threadIdx.x;            // 1024 threads, 8 counters each
    int base = tid * 8;
    int c[8], s = 0;
    #pragma unroll
    for (int j = 0; j < 8; j++) { c[j] = g_cnt[base + j]; s += c[j]; }
    int lane = tid & 31, w = tid >> 5;
    int v = s;
    #pragma unroll
    for (int o = 1; o < 32; o <<= 1) {
        int t = __shfl_up_sync(0xffffffffu, v, o);
        if (lane >= o) v += t;
    }
    if (lane == 31) warp_sums[w] = v;
    __syncthreads();
    if (w == 0) {
        int ws = warp_sums[lane];
        #pragma unroll
        for (int o = 1; o < 32; o <<= 1) {
            int t = __shfl_up_sync(0xffffffffu, ws, o);
            if (lane >= o) ws += t;
        }
        warp_sums[lane] = ws;
    }
    __syncthreads();
    int run = v - s + (w > 0 ? warp_sums[w - 1] : 0);
    #pragma unroll
    for (int j = 0; j < 8; j++) {
        g_startA[base + j] = run;
        g_cursor[base + j] = run;
        g_dis[base + j]    = rsqrtf((float)(c[j] + 1));
        run += c[j];
    }
    if (tid == 1023) g_startA[N] = E;
}

// ----------------- chain B3: CSR fill, wide grid, global atomic cursors
__global__ void k_fill(const int* __restrict__ ei) {
    int i = blockIdx.x * blockDim.x + threadIdx.x;
    int r = __ldg(&ei[i]);
    int c = __ldg(&ei[E + i]);
    g_csr[atomicAdd(&g_cursor[c], 1)] = r;
}

// ----------------- main A1: M = Y^T x (128x128) with fused row norms
__global__ void k_maccum(const float* __restrict__ x) {
    __shared__ float xs[8][DIM];
    __shared__ float invs[8];
    int tid = threadIdx.x;
    int tx = tid & 15, ty = tid >> 4;
    int k0 = ty * 8, d0 = tx * 8;
    float acc[8][8] = {};
    int row_base = blockIdx.x * 64;
    for (int p = 0; p < 8; p++) {
        int r0 = row_base + p * 8;
        {   // warp rr stages row r0+rr and computes its inverse norm
            int rr = tid >> 5, cc = tid & 31;
            float4 v = ((const float4*)x)[(r0 + rr) * 32 + cc];
            ((float4*)&xs[rr][0])[cc] = v;
            float s = v.x * v.x + v.y * v.y + v.z * v.z + v.w * v.w;
            #pragma unroll
            for (int o = 16; o; o >>= 1) s += __shfl_xor_sync(0xffffffffu, s, o);
            if (cc == 0) {
                float inv = rsqrtf(s);
                invs[rr] = inv;
                g_inv_nrm[r0 + rr] = inv;
            }
        }
        __syncthreads();
        #pragma unroll
        for (int r = 0; r < 8; r++) {
            float inv = invs[r];
            float yk[8], xd[8];
            #pragma unroll
            for (int j = 0; j < 8; j++) yk[j] = xs[r][k0 + j] * inv;
            #pragma unroll
            for (int l = 0; l < 8; l++) xd[l] = xs[r][d0 + l];
            #pragma unroll
            for (int j = 0; j < 8; j++)
                #pragma unroll
                for (int l = 0; l < 8; l++)
                    acc[j][l] += yk[j] * xd[l];
        }
        __syncthreads();
    }
    #pragma unroll
    for (int j = 0; j < 8; j++)
        #pragma unroll
        for (int l = 0; l < 8; l++)
            atomicAdd(&g_M[(k0 + j) * DIM + (d0 + l)], acc[j][l]);
}

// ----------------- GEMM P = x @ B: 32-row tiles, grid 256, 2 blocks/SM
// mode 0: B=W   -> g_dxw  (unscaled)
// mode 1: B=g_M -> g_gate = sigmoid(P * inv_nrm[row])
__global__ void __launch_bounds__(256) k_gemm(const float* __restrict__ x,
                                              const float* __restrict__ Bp,
                                              int mode) {
    extern __shared__ float sm[];
    float* As = sm;                    // [32][ASTR]
    float* Bs = sm + 32 * ASTR;        // [128][128]
    int tid = threadIdx.x;
    int tx = tid & 31, ty = tid >> 5;  // tx: float4 col, ty: 4-row group
    int rb = blockIdx.x * 32;
    const float* B = (mode == 0) ? Bp : g_M;

    #pragma unroll
    for (int i = 0; i < 4; i++) {      // A: 32 rows x 32 float4 = 1024
        int f = i * 256 + tid;
        int row = f >> 5, c4 = f & 31;
        float4 v = ((const float4*)x)[(rb + row) * 32 + c4];
        *((float4*)&As[row * ASTR + c4 * 4]) = v;
    }
    #pragma unroll
    for (int i = 0; i < 16; i++) {     // B: 4096 float4
        int f = i * 256 + tid;
        ((float4*)Bs)[f] = ((const float4*)B)[f];
    }
    __syncthreads();

    int r0 = ty * 4;
    float4 acc[4];
    #pragma unroll
    for (int i = 0; i < 4; i++) acc[i] = make_float4(0.f, 0.f, 0.f, 0.f);
    #pragma unroll 8
    for (int k = 0; k < DIM; k++) {
        float4 bv = ((float4*)Bs)[k * 32 + tx];
        #pragma unroll
        for (int i = 0; i < 4; i++) {
            float a = As[(r0 + i) * ASTR + k];   // warp-broadcast LDS
            acc[i].x += a * bv.x; acc[i].y += a * bv.y;
            acc[i].z += a * bv.z; acc[i].w += a * bv.w;
        }
    }

    if (mode == 0) {
        #pragma unroll
        for (int i = 0; i < 4; i++)
            ((float4*)g_dxw)[(rb + r0 + i) * 32 + tx] = acc[i];
    } else {
        #pragma unroll
        for (int i = 0; i < 4; i++) {
            int grow = rb + r0 + i;
            float s = g_inv_nrm[grow];
            float4 o;
            o.x = 1.f / (1.f + __expf(-acc[i].x * s));
            o.y = 1.f / (1.f + __expf(-acc[i].y * s));
            o.z = 1.f / (1.f + __expf(-acc[i].z * s));
            o.w = 1.f / (1.f + __expf(-acc[i].w * s));
            ((float4*)g_gate)[grow * 32 + tx] = o;
        }
    }
}

// ----------------- join: CSR gather + gate + bias; self-clean g_M/g_cnt
__global__ void k_final(const float* __restrict__ b, float* __restrict__ out) {
    int tid = threadIdx.x;
    int gtid = blockIdx.x * 256 + tid;
    // self-clean for next replay (nothing below reads g_M / g_cnt)
    if (gtid < DIM * DIM) g_M[gtid] = 0.f;
    if (gtid < N) g_cnt[gtid] = 0;

    int w = tid >> 5, lane = tid & 31;
    int node = blockIdx.x * 8 + w;
    const float4* dxw4 = (const float4*)g_dxw;

    int s0  = g_startA[node];
    int cnt = g_startA[node + 1] - s0;
    float dn = g_dis[node];
    float4 self = dxw4[node * 32 + lane];
    float4 acc;
    acc.x = self.x * dn; acc.y = self.y * dn;
    acc.z = self.z * dn; acc.w = self.w * dn;
    int j = 0;
    for (; j + 4 <= cnt; j += 4) {
        int i0 = __ldg(&g_csr[s0 + j]);
        int i1 = __ldg(&g_csr[s0 + j + 1]);
        int i2 = __ldg(&g_csr[s0 + j + 2]);
        int i3 = __ldg(&g_csr[s0 + j + 3]);
        float d0 = __ldg(&g_dis[i0]), d1 = __ldg(&g_dis[i1]);
        float d2 = __ldg(&g_dis[i2]), d3 = __ldg(&g_dis[i3]);
        float4 v0 = dxw4[i0 * 32 + lane];
        float4 v1 = dxw4[i1 * 32 + lane];
        float4 v2 = dxw4[i2 * 32 + lane];
        float4 v3 = dxw4[i3 * 32 + lane];
        acc.x += v0.x * d0 + v1.x * d1 + v2.x * d2 + v3.x * d3;
        acc.y += v0.y * d0 + v1.y * d1 + v2.y * d2 + v3.y * d3;
        acc.z += v0.z * d0 + v1.z * d1 + v2.z * d2 + v3.z * d3;
        acc.w += v0.w * d0 + v1.w * d1 + v2.w * d2 + v3.w * d3;
    }
    for (; j < cnt; j++) {
        int i0 = __ldg(&g_csr[s0 + j]);
        float d0 = __ldg(&g_dis[i0]);
        float4 v0 = dxw4[i0 * 32 + lane];
        acc.x += v0.x * d0; acc.y += v0.y * d0;
        acc.z += v0.z * d0; acc.w += v0.w * d0;
    }
    float4 bb = ((const float4*)b)[lane];
    float4 a  = ((const float4*)g_gate)[node * 32 + lane];
    float4 o;
    o.x = (acc.x * dn + bb.x) * a.x;
    o.y = (acc.y * dn + bb.y) * a.y;
    o.z = (acc.z * dn + bb.z) * a.z;
    o.w = (acc.w * dn + bb.w) * a.w;
    ((float4*)out)[node * 32 + lane] = o;
}

// ---------------------------------------------------------------- launcher
extern "C" void kernel_launch(void* const* d_in, const int* in_sizes, int n_in,
                              void* d_out, int out_size) {
    const float* x  = (const float*)d_in[0];
    const int*   ei = (const int*)d_in[1];
    const float* W  = (const float*)d_in[2];
    const float* b  = (const float*)d_in[3];
    float* out = (float*)d_out;

    const int SMEM_G = (32 * ASTR + 128 * 128) * 4;   // ~82.4 KB -> 2 blocks/SM
    static bool init_done = false;
    static cudaStream_t sB, sC;
    static cudaEvent_t evRoot, evB, evC;
    if (!init_done) {
        cudaStreamCreateWithFlags(&sB, cudaStreamNonBlocking);
        cudaStreamCreateWithFlags(&sC, cudaStreamNonBlocking);
        cudaEventCreateWithFlags(&evRoot, cudaEventDisableTiming);
        cudaEventCreateWithFlags(&evB,    cudaEventDisableTiming);
        cudaEventCreateWithFlags(&evC,    cudaEventDisableTiming);
        cudaFuncSetAttribute(k_gemm, cudaFuncAttributeMaxDynamicSharedMemorySize, SMEM_G);
        init_done = true;
    }

    // fork
    cudaEventRecord(evRoot, 0);
    cudaStreamWaitEvent(sB, evRoot, 0);
    cudaStreamWaitEvent(sC, evRoot, 0);

    // chain B: CSR build (latency-bound; overlaps compute)
    k_hist<<<E / 256, 256, 0, sB>>>(ei);
    k_scan<<<1, 1024, 0, sB>>>();
    k_fill<<<E / 256, 256, 0, sB>>>(ei);
    cudaEventRecord(evB, sB);

    // chain C: x @ W (no dependencies)
    k_gemm<<<N / 32, 256, SMEM_G, sC>>>(x, W, 0);
    cudaEventRecord(evC, sC);

    // main chain: maccum(+norms) -> gate gemm
    k_maccum<<<128, 256>>>(x);
    k_gemm  <<<N / 32, 256, SMEM_G>>>(x, nullptr, 1);

    // join
    cudaStreamWaitEvent(0, evB, 0);
    cudaStreamWaitEvent(0, evC, 0);
    k_final<<<N / 8, 256>>>(b, out);
}